// round 1
// baseline (speedup 1.0000x reference)
#include <cuda_runtime.h>
#include <cuda_bf16.h>
#include <float.h>
#include <math.h>

#define LANE_WEIGHT 1.0f
#define INV_TEMP    10.0f   // 1 / 0.1

// scratch (allocation-free rule: __device__ globals)
__device__ float g_ce_lane[65536];      // ce_per_lane, NL <= 65536
__device__ float g_sample_loss[8192];   // per-sample loss, B <= 8192

// ---------------------------------------------------------------------------
// Kernel 1: one block per lane. Computes trajectory scores (ADE) for the
// lane's K trajectories, then the fused softmax-CE:
//   ce = tmax + log(sum exp(ts - tmax)) - (sum p*ts) / (sum p)
// with p = exp((score - smax) * INV_TEMP).
// ---------------------------------------------------------------------------
__global__ __launch_bounds__(256)
void traj_ce_kernel(const float* __restrict__ traj_scores,   // [NT]
                    const float* __restrict__ cand,          // [NT, T, 2]
                    const float* __restrict__ gt,            // [B, T, 2]
                    const float* __restrict__ scales,        // [B]
                    const int*   __restrict__ cls_se,        // [B, 2]
                    const int*   __restrict__ trj_se,        // [NL, 2]
                    int B, int T)
{
    const int lane = blockIdx.x;
    const int tid  = threadIdx.x;

    const int ts_start = trj_se[2 * lane];
    const int ts_end   = trj_se[2 * lane + 1];
    int cnt = ts_end - ts_start;
    if (cnt > 64) cnt = 64;   // smem sizing guard (K=64 in this problem)

    // sample id = last b with cls_se[2b] <= lane  (starts are sorted)
    int lo = 0, hi = B - 1;
    while (lo < hi) {
        int mid = (lo + hi + 1) >> 1;
        if (cls_se[2 * mid] <= lane) lo = mid; else hi = mid - 1;
    }
    const int sample = lo;

    __shared__ __align__(8) float s_gt[1024];   // T*2 floats (T <= 512)
    __shared__ float s_score[64];
    __shared__ float s_ts[64];
    __shared__ float ra[64], rb[64], rc[64];

    const int t2 = T * 2;
    for (int i = tid; i < t2 && i < 1024; i += blockDim.x)
        s_gt[i] = gt[(size_t)sample * t2 + i];
    __syncthreads();

    const float inv_scale = 1.0f / scales[sample];

    // 4 threads per trajectory
    const int q   = tid >> 2;
    const int sub = tid & 3;
    float acc = 0.0f;
    if (q < cnt) {
        const float2* base = reinterpret_cast<const float2*>(cand)
                             + (size_t)(ts_start + q) * T;
        const float2* g2 = reinterpret_cast<const float2*>(s_gt);
        for (int t = sub; t < T; t += 4) {
            float2 c = base[t];
            float2 g = g2[t];
            float dx = c.x - g.x;
            float dy = c.y - g.y;
            acc += sqrtf(fmaf(dx, dx, fmaf(dy, dy, 1e-12f)));
        }
    }
    // reduce within the quad (groups are shfl-aligned)
    acc += __shfl_xor_sync(0xffffffffu, acc, 1);
    acc += __shfl_xor_sync(0xffffffffu, acc, 2);

    if (sub == 0 && q < cnt) {
        float ade = acc / (float)T;
        s_score[q] = -ade * inv_scale;
        s_ts[q]    = traj_scores[ts_start + q];
    }
    __syncthreads();

    // ---- pass A: maxes of score and ts over cnt elements ----
    if (tid < 64) {
        ra[tid] = (tid < cnt) ? s_score[tid] : -FLT_MAX;
        rb[tid] = (tid < cnt) ? s_ts[tid]    : -FLT_MAX;
    }
    __syncthreads();
    if (tid < 32) {
        float a = fmaxf(ra[tid], ra[tid + 32]);
        float b = fmaxf(rb[tid], rb[tid + 32]);
        #pragma unroll
        for (int o = 16; o; o >>= 1) {
            a = fmaxf(a, __shfl_xor_sync(0xffffffffu, a, o));
            b = fmaxf(b, __shfl_xor_sync(0xffffffffu, b, o));
        }
        if (tid == 0) { ra[0] = a; rb[0] = b; }
    }
    __syncthreads();
    const float smax = ra[0];
    const float tmax = rb[0];
    __syncthreads();

    // ---- pass B: three sums ----
    float p = 0.0f, ets = 0.0f, pts = 0.0f;
    if (tid < cnt) {
        p   = expf((s_score[tid] - smax) * INV_TEMP);
        ets = expf(s_ts[tid] - tmax);
        pts = p * s_ts[tid];
    }
    if (tid < 64) { ra[tid] = p; rb[tid] = ets; rc[tid] = pts; }
    __syncthreads();
    if (tid < 32) {
        float a = ra[tid] + ra[tid + 32];
        float b = rb[tid] + rb[tid + 32];
        float c = rc[tid] + rc[tid + 32];
        #pragma unroll
        for (int o = 16; o; o >>= 1) {
            a += __shfl_xor_sync(0xffffffffu, a, o);
            b += __shfl_xor_sync(0xffffffffu, b, o);
            c += __shfl_xor_sync(0xffffffffu, c, o);
        }
        if (tid == 0)
            g_ce_lane[lane] = tmax + logf(b) - c / a;
    }
}

// ---------------------------------------------------------------------------
// Kernel 2: one warp per sample. Lane-level CE + oracle-weighted traj loss.
// ---------------------------------------------------------------------------
__global__ __launch_bounds__(32)
void sample_loss_kernel(const float* __restrict__ lane_scores,  // [NL]
                        const int*   __restrict__ oracle,       // [NL] (nonzero = true)
                        const int*   __restrict__ cls_se)       // [B, 2]
{
    const int b = blockIdx.x;
    const int i = threadIdx.x;
    const int s = cls_se[2 * b];
    const int e = cls_se[2 * b + 1];
    int cnt = e - s;
    if (cnt > 32) cnt = 32;   // L=16 in this problem

    const bool act = (i < cnt);
    float ls  = act ? lane_scores[s + i] : -FLT_MAX;
    bool  orc = act && (oracle[s + i] != 0);
    float ce  = orc ? g_ce_lane[s + i] : 0.0f;

    // warp max of ls
    float m = ls;
    #pragma unroll
    for (int o = 16; o; o >>= 1) m = fmaxf(m, __shfl_xor_sync(0xffffffffu, m, o));

    float ev   = act ? expf(ls - m) : 0.0f;
    float oc   = orc ? 1.0f : 0.0f;
    float llc  = orc ? 0.0f : 0.0f;  // filled below after lse

    float Z = ev, OC = oc, CE = ce;
    #pragma unroll
    for (int o = 16; o; o >>= 1) {
        Z  += __shfl_xor_sync(0xffffffffu, Z, o);
        OC += __shfl_xor_sync(0xffffffffu, OC, o);
        CE += __shfl_xor_sync(0xffffffffu, CE, o);
    }
    const float lse = logf(Z);
    // -target * logp, target = orc / OC, logp = ls - m - lse
    llc = orc ? (m + lse - ls) : 0.0f;
    float LL = llc;
    #pragma unroll
    for (int o = 16; o; o >>= 1) LL += __shfl_xor_sync(0xffffffffu, LL, o);

    if (i == 0) {
        float lane_loss = (LL / OC) * LANE_WEIGHT;
        float traj_loss = CE / OC;
        g_sample_loss[b] = lane_loss + traj_loss;
    }
}

// ---------------------------------------------------------------------------
// Kernel 3: mean over B samples -> d_out[0]
// ---------------------------------------------------------------------------
__global__ __launch_bounds__(256)
void final_mean_kernel(float* __restrict__ out, int B)
{
    __shared__ float red[256];
    const int tid = threadIdx.x;
    float v = 0.0f;
    for (int i = tid; i < B; i += 256) v += g_sample_loss[i];
    red[tid] = v;
    __syncthreads();
    for (int o = 128; o >= 32; o >>= 1) {
        if (tid < o) red[tid] += red[tid + o];
        __syncthreads();
    }
    if (tid < 32) {
        float a = red[tid];
        #pragma unroll
        for (int o = 16; o; o >>= 1) a += __shfl_xor_sync(0xffffffffu, a, o);
        if (tid == 0) out[0] = a / (float)B;
    }
}

// ---------------------------------------------------------------------------
extern "C" void kernel_launch(void* const* d_in, const int* in_sizes, int n_in,
                              void* d_out, int out_size)
{
    const float* lane_scores = (const float*)d_in[0];   // [NL]
    const float* traj_scores = (const float*)d_in[1];   // [NT, 1]
    const float* cand        = (const float*)d_in[2];   // [NT, T, 2]
    const float* gt          = (const float*)d_in[3];   // [B, T, 2]
    const float* scales      = (const float*)d_in[4];   // [B]
    const int*   oracle      = (const int*)  d_in[5];   // [NL]
    const int*   cls_se      = (const int*)  d_in[6];   // [B, 2]
    const int*   trj_se      = (const int*)  d_in[7];   // [NL, 2]

    const int NL = in_sizes[0];
    const int B  = in_sizes[6] / 2;
    const int T  = in_sizes[3] / (2 * B);

    traj_ce_kernel<<<NL, 256>>>(traj_scores, cand, gt, scales, cls_se, trj_se, B, T);
    sample_loss_kernel<<<B, 32>>>(lane_scores, oracle, cls_se);
    final_mean_kernel<<<1, 256>>>((float*)d_out, B);
}

// round 2
// speedup vs baseline: 1.2391x; 1.2391x over previous
#include <cuda_runtime.h>
#include <cuda_bf16.h>
#include <float.h>
#include <math.h>

#define LANE_WEIGHT 1.0f
#define INV_TEMP    10.0f   // 1 / 0.1

// scratch (allocation-free rule: __device__ globals)
__device__ float g_ce_lane[65536];      // ce_per_lane, NL <= 65536
__device__ float g_sample_loss[8192];   // per-sample loss, B <= 8192

// ---------------------------------------------------------------------------
// Shared epilogue: fused softmax CE over cnt (<=64) entries in s_score/s_ts.
//   ce = tmax + log(sum exp(ts - tmax)) - (sum p*ts) / (sum p)
// with p = exp((score - smax) * INV_TEMP).  Writes g_ce_lane[lane].
// ---------------------------------------------------------------------------
__device__ __forceinline__
void lane_ce_epilogue(int lane, int cnt, int tid,
                      const float* s_score, const float* s_ts,
                      float* ra, float* rb, float* rc)
{
    // ---- pass A: maxes ----
    if (tid < 64) {
        ra[tid] = (tid < cnt) ? s_score[tid] : -FLT_MAX;
        rb[tid] = (tid < cnt) ? s_ts[tid]    : -FLT_MAX;
    }
    __syncthreads();
    if (tid < 32) {
        float a = fmaxf(ra[tid], ra[tid + 32]);
        float b = fmaxf(rb[tid], rb[tid + 32]);
        #pragma unroll
        for (int o = 16; o; o >>= 1) {
            a = fmaxf(a, __shfl_xor_sync(0xffffffffu, a, o));
            b = fmaxf(b, __shfl_xor_sync(0xffffffffu, b, o));
        }
        if (tid == 0) { ra[0] = a; rb[0] = b; }
    }
    __syncthreads();
    const float smax = ra[0];
    const float tmax = rb[0];
    __syncthreads();

    // ---- pass B: three sums ----
    float p = 0.0f, ets = 0.0f, pts = 0.0f;
    if (tid < cnt) {
        float ts = s_ts[tid];
        p   = expf((s_score[tid] - smax) * INV_TEMP);
        ets = expf(ts - tmax);
        pts = p * ts;
    }
    if (tid < 64) { ra[tid] = p; rb[tid] = ets; rc[tid] = pts; }
    __syncthreads();
    if (tid < 32) {
        float a = ra[tid] + ra[tid + 32];
        float b = rb[tid] + rb[tid + 32];
        float c = rc[tid] + rc[tid + 32];
        #pragma unroll
        for (int o = 16; o; o >>= 1) {
            a += __shfl_xor_sync(0xffffffffu, a, o);
            b += __shfl_xor_sync(0xffffffffu, b, o);
            c += __shfl_xor_sync(0xffffffffu, c, o);
        }
        if (tid == 0)
            g_ce_lane[lane] = tmax + logf(b) - c / a;
    }
}

__device__ __forceinline__
int find_sample(const int* __restrict__ cls_se, int B, int lane)
{
    int lo = 0, hi = B - 1;
    while (lo < hi) {
        int mid = (lo + hi + 1) >> 1;
        if (cls_se[2 * mid] <= lane) lo = mid; else hi = mid - 1;
    }
    return lo;
}

// ---------------------------------------------------------------------------
// Fast kernel for T == 50: one block per lane, fully coalesced float4 stream
// of the lane's contiguous candidate region with compile-time-unrolled loads.
// ---------------------------------------------------------------------------
__global__ __launch_bounds__(256, 6)
void traj_ce_T50_kernel(const float* __restrict__ traj_scores,   // [NT]
                        const float* __restrict__ cand,          // [NT, 50, 2]
                        const float* __restrict__ gt,            // [B, 50, 2]
                        const float* __restrict__ scales,        // [B]
                        const int*   __restrict__ cls_se,        // [B, 2]
                        const int*   __restrict__ trj_se,        // [NL, 2]
                        int B)
{
    const int lane = blockIdx.x;
    const int tid  = threadIdx.x;

    const int ts_start = trj_se[2 * lane];
    const int ts_end   = trj_se[2 * lane + 1];
    int cnt = ts_end - ts_start;
    if (cnt > 64) cnt = 64;

    const int sample = find_sample(cls_se, B, lane);

    __shared__ __align__(8) float2 s_gt[50];
    __shared__ float s_sum[1600];             // one partial per float4 (2 points)
    __shared__ float s_score[64], s_ts[64];
    __shared__ float ra[64], rb[64], rc[64];

    if (tid < 50)
        s_gt[tid] = reinterpret_cast<const float2*>(gt)[sample * 50 + tid];
    const float inv_scale = 1.0f / scales[sample];
    __syncthreads();

    // Phase 1: coalesced float4 stream.  One lane region = cnt*25 float4.
    const int n4 = cnt * 25;
    const float4* src = reinterpret_cast<const float4*>(cand)
                        + (size_t)ts_start * 25;
    #pragma unroll
    for (int k = 0; k < 7; k++) {
        const int f = tid + 256 * k;
        if (f < n4) {
            float4 v = src[f];
            const int r  = f % 25;       // float4 index within trajectory
            const int t0 = 2 * r;        // first of the two timesteps
            float2 g0 = s_gt[t0];
            float2 g1 = s_gt[t0 + 1];
            float dx0 = v.x - g0.x, dy0 = v.y - g0.y;
            float dx1 = v.z - g1.x, dy1 = v.w - g1.y;
            s_sum[f] = sqrtf(fmaf(dx0, dx0, fmaf(dy0, dy0, 1e-12f)))
                     + sqrtf(fmaf(dx1, dx1, fmaf(dy1, dy1, 1e-12f)));
        }
    }
    __syncthreads();

    // Phase 2: per-trajectory sum (stride 25 vs 32 banks -> conflict-free)
    if (tid < cnt) {
        float s = 0.0f;
        #pragma unroll
        for (int i = 0; i < 25; i++) s += s_sum[25 * tid + i];
        float ade = s * 0.02f;           // / 50
        s_score[tid] = -ade * inv_scale;
        s_ts[tid]    = traj_scores[ts_start + tid];
    }
    __syncthreads();

    lane_ce_epilogue(lane, cnt, tid, s_score, s_ts, ra, rb, rc);
}

// ---------------------------------------------------------------------------
// Generic fallback (any T): 4 threads per trajectory, float2 loads.
// ---------------------------------------------------------------------------
__global__ __launch_bounds__(256)
void traj_ce_kernel(const float* __restrict__ traj_scores,
                    const float* __restrict__ cand,
                    const float* __restrict__ gt,
                    const float* __restrict__ scales,
                    const int*   __restrict__ cls_se,
                    const int*   __restrict__ trj_se,
                    int B, int T)
{
    const int lane = blockIdx.x;
    const int tid  = threadIdx.x;

    const int ts_start = trj_se[2 * lane];
    const int ts_end   = trj_se[2 * lane + 1];
    int cnt = ts_end - ts_start;
    if (cnt > 64) cnt = 64;

    const int sample = find_sample(cls_se, B, lane);

    __shared__ __align__(8) float s_gt[1024];
    __shared__ float s_score[64], s_ts[64];
    __shared__ float ra[64], rb[64], rc[64];

    const int t2 = T * 2;
    for (int i = tid; i < t2 && i < 1024; i += blockDim.x)
        s_gt[i] = gt[(size_t)sample * t2 + i];
    __syncthreads();

    const float inv_scale = 1.0f / scales[sample];

    const int q   = tid >> 2;
    const int sub = tid & 3;
    float acc = 0.0f;
    if (q < cnt) {
        const float2* base = reinterpret_cast<const float2*>(cand)
                             + (size_t)(ts_start + q) * T;
        const float2* g2 = reinterpret_cast<const float2*>(s_gt);
        #pragma unroll 4
        for (int t = sub; t < T; t += 4) {
            float2 c = base[t];
            float2 g = g2[t];
            float dx = c.x - g.x;
            float dy = c.y - g.y;
            acc += sqrtf(fmaf(dx, dx, fmaf(dy, dy, 1e-12f)));
        }
    }
    acc += __shfl_xor_sync(0xffffffffu, acc, 1);
    acc += __shfl_xor_sync(0xffffffffu, acc, 2);

    if (sub == 0 && q < cnt) {
        float ade = acc / (float)T;
        s_score[q] = -ade * inv_scale;
        s_ts[q]    = traj_scores[ts_start + q];
    }
    __syncthreads();

    lane_ce_epilogue(lane, cnt, tid, s_score, s_ts, ra, rb, rc);
}

// ---------------------------------------------------------------------------
// Kernel 2: one warp per sample. Lane-level CE + oracle-weighted traj loss.
// ---------------------------------------------------------------------------
__global__ __launch_bounds__(32)
void sample_loss_kernel(const float* __restrict__ lane_scores,  // [NL]
                        const int*   __restrict__ oracle,       // [NL] (nonzero = true)
                        const int*   __restrict__ cls_se)       // [B, 2]
{
    const int b = blockIdx.x;
    const int i = threadIdx.x;
    const int s = cls_se[2 * b];
    const int e = cls_se[2 * b + 1];
    int cnt = e - s;
    if (cnt > 32) cnt = 32;   // L=16 in this problem

    const bool act = (i < cnt);
    float ls  = act ? lane_scores[s + i] : -FLT_MAX;
    bool  orc = act && (oracle[s + i] != 0);
    float ce  = orc ? g_ce_lane[s + i] : 0.0f;

    float m = ls;
    #pragma unroll
    for (int o = 16; o; o >>= 1) m = fmaxf(m, __shfl_xor_sync(0xffffffffu, m, o));

    float ev = act ? expf(ls - m) : 0.0f;
    float oc = orc ? 1.0f : 0.0f;

    float Z = ev, OC = oc, CE = ce;
    #pragma unroll
    for (int o = 16; o; o >>= 1) {
        Z  += __shfl_xor_sync(0xffffffffu, Z, o);
        OC += __shfl_xor_sync(0xffffffffu, OC, o);
        CE += __shfl_xor_sync(0xffffffffu, CE, o);
    }
    const float lse = logf(Z);
    float llc = orc ? (m + lse - ls) : 0.0f;   // -target*logp numerator
    float LL = llc;
    #pragma unroll
    for (int o = 16; o; o >>= 1) LL += __shfl_xor_sync(0xffffffffu, LL, o);

    if (i == 0) {
        float lane_loss = (LL / OC) * LANE_WEIGHT;
        float traj_loss = CE / OC;
        g_sample_loss[b] = lane_loss + traj_loss;
    }
}

// ---------------------------------------------------------------------------
// Kernel 3: mean over B samples -> d_out[0]
// ---------------------------------------------------------------------------
__global__ __launch_bounds__(256)
void final_mean_kernel(float* __restrict__ out, int B)
{
    __shared__ float red[256];
    const int tid = threadIdx.x;
    float v = 0.0f;
    for (int i = tid; i < B; i += 256) v += g_sample_loss[i];
    red[tid] = v;
    __syncthreads();
    for (int o = 128; o >= 32; o >>= 1) {
        if (tid < o) red[tid] += red[tid + o];
        __syncthreads();
    }
    if (tid < 32) {
        float a = red[tid];
        #pragma unroll
        for (int o = 16; o; o >>= 1) a += __shfl_xor_sync(0xffffffffu, a, o);
        if (tid == 0) out[0] = a / (float)B;
    }
}

// ---------------------------------------------------------------------------
extern "C" void kernel_launch(void* const* d_in, const int* in_sizes, int n_in,
                              void* d_out, int out_size)
{
    const float* lane_scores = (const float*)d_in[0];   // [NL]
    const float* traj_scores = (const float*)d_in[1];   // [NT, 1]
    const float* cand        = (const float*)d_in[2];   // [NT, T, 2]
    const float* gt          = (const float*)d_in[3];   // [B, T, 2]
    const float* scales      = (const float*)d_in[4];   // [B]
    const int*   oracle      = (const int*)  d_in[5];   // [NL]
    const int*   cls_se      = (const int*)  d_in[6];   // [B, 2]
    const int*   trj_se      = (const int*)  d_in[7];   // [NL, 2]

    const int NL = in_sizes[0];
    const int B  = in_sizes[6] / 2;
    const int T  = in_sizes[3] / (2 * B);

    if (T == 50) {
        traj_ce_T50_kernel<<<NL, 256>>>(traj_scores, cand, gt, scales,
                                        cls_se, trj_se, B);
    } else {
        traj_ce_kernel<<<NL, 256>>>(traj_scores, cand, gt, scales,
                                    cls_se, trj_se, B, T);
    }
    sample_loss_kernel<<<B, 32>>>(lane_scores, oracle, cls_se);
    final_mean_kernel<<<1, 256>>>((float*)d_out, B);
}